// round 1
// baseline (speedup 1.0000x reference)
#include <cuda_runtime.h>
#include <math.h>

// Global double accumulator (allocation-free scratch).
__device__ double g_acc;

__global__ void zero_acc_kernel() { g_acc = 0.0; }

// Shapes fixed by the problem.
#define BN 16
#define HH 480
#define WW 640
#define HW (HH * WW)
#define HW4 (HW / 4)

__global__ __launch_bounds__(256) void cheirality_kernel(
    const float* __restrict__ pose,
    const float* __restrict__ grad,
    const float* __restrict__ nf)
{
    const int b = blockIdx.y;

    // pose[b, 0:3] = V, pose[b, 3:6] = Omega
    const float V0 = __ldg(pose + b * 6 + 0);
    const float V1 = __ldg(pose + b * 6 + 1);
    const float V2 = __ldg(pose + b * 6 + 2);
    const float O0 = __ldg(pose + b * 6 + 3);
    const float O1 = __ldg(pose + b * 6 + 4);
    const float O2 = __ldg(pose + b * 6 + 5);

    const float4* __restrict__ g0p = (const float4*)(grad + (size_t)b * 2 * HW);
    const float4* __restrict__ g1p = g0p + HW4;
    const float4* __restrict__ n0p = (const float4*)(nf + (size_t)b * 2 * HW);
    const float4* __restrict__ n1p = n0p + HW4;

    double acc = 0.0;
    const int stride = gridDim.x * blockDim.x;

    for (int i = blockIdx.x * blockDim.x + threadIdx.x; i < HW4; i += stride) {
        float4 g0 = g0p[i];
        float4 g1 = g1p[i];
        float4 n0 = n0p[i];
        float4 n1 = n1p[i];

        int p  = i * 4;
        int h  = p / WW;
        int w0 = p - h * WW;     // all 4 lanes share row h
        float y = (float)h;

        // Per-row invariants
        float AV1  = fmaf(y, V2, -V1);               // -V1 + y*V2
        float y2p1 = fmaf(y, y, 1.0f);

        const float* ga = &g0.x;
        const float* gb = &g1.x;
        const float* na = &n0.x;
        const float* nb = &n1.x;

        float s4 = 0.0f;  // unused; keep per-lane values separate below
        (void)s4;

        #pragma unroll
        for (int j = 0; j < 4; j++) {
            float x  = (float)(w0 + j);
            float xy = x * y;

            float AV0 = fmaf(x, V2, -V0);                    // -V0 + x*V2
            // BW0 = xy*O0 - (x^2+1)*O1 + y*O2
            float BW0 = fmaf(xy, O0, fmaf(-fmaf(x, x, 1.0f), O1, y * O2));
            // BW1 = (y^2+1)*O0 - xy*O1 - x*O2
            float BW1 = fmaf(y2p1, O0, fmaf(-xy, O1, -x * O2));

            float gg0 = ga[j], gg1 = gb[j];
            float s = fmaf(gg0, AV0, gg1 * AV1);
            float t = (na[j] + nb[j]) - fmaf(gg0, BW0, gg1 * BW1);
            float z = -(s * t);

            // exact GELU: z * Phi(z)
            float val = z * normcdff(z);
            acc += (double)val;
        }
    }

    // Block reduction in double.
    __shared__ double warp_sums[8];
    unsigned mask = 0xFFFFFFFFu;
    #pragma unroll
    for (int off = 16; off > 0; off >>= 1)
        acc += __shfl_down_sync(mask, acc, off);

    int lane = threadIdx.x & 31;
    int wid  = threadIdx.x >> 5;
    if (lane == 0) warp_sums[wid] = acc;
    __syncthreads();

    if (wid == 0) {
        double v = (lane < 8) ? warp_sums[lane] : 0.0;
        #pragma unroll
        for (int off = 4; off > 0; off >>= 1)
            v += __shfl_down_sync(mask, v, off);
        if (lane == 0) atomicAdd(&g_acc, v);
    }
}

__global__ void finalize_kernel(float* out) {
    out[0] = (float)(g_acc / (double)((long long)BN * HW));
}

extern "C" void kernel_launch(void* const* d_in, const int* in_sizes, int n_in,
                              void* d_out, int out_size) {
    const float* pose = (const float*)d_in[0];
    const float* grad = (const float*)d_in[1];
    const float* nf   = (const float*)d_in[2];
    float* out = (float*)d_out;

    zero_acc_kernel<<<1, 1>>>();
    dim3 grid(75, BN);              // 75*256 = 19200 threads/plane; HW4/19200 = 4 iters
    cheirality_kernel<<<grid, 256>>>(pose, grad, nf);
    finalize_kernel<<<1, 1>>>(out);
}

// round 2
// speedup vs baseline: 1.5663x; 1.5663x over previous
#include <cuda_runtime.h>
#include <math.h>

#define BN 16
#define HH 480
#define WW 640
#define HW (HH * WW)
#define HW4 (HW / 4)          // 76800 float4 per plane
#define GX 75
#define TPB 256
#define NBLK (GX * BN)        // 1200 blocks
#define STRIDE4 (GX * TPB)    // 19200 float4 stride
#define ITERS (HW4 / STRIDE4) // exactly 4
#define W4 (WW / 4)           // 160 float4 per row
#define ROWS_PER_ITER (STRIDE4 / W4) // 120

// Allocation-free scratch.
__device__ float g_partials[NBLK];
__device__ unsigned int g_count = 0;

__global__ __launch_bounds__(TPB) void cheirality_fused(
    const float* __restrict__ pose,
    const float* __restrict__ grad,
    const float* __restrict__ nf,
    float* __restrict__ out)
{
    const int b   = blockIdx.y;
    const int tid = threadIdx.x;

    // pose[b,0:3]=V, pose[b,3:6]=Omega
    const float V0 = __ldg(pose + b * 6 + 0);
    const float V1 = __ldg(pose + b * 6 + 1);
    const float V2 = __ldg(pose + b * 6 + 2);
    const float O0 = __ldg(pose + b * 6 + 3);
    const float O1 = __ldg(pose + b * 6 + 4);
    const float O2 = __ldg(pose + b * 6 + 5);

    const float4* __restrict__ g0p = (const float4*)(grad + (size_t)b * 2 * HW);
    const float4* __restrict__ g1p = g0p + HW4;
    const float4* __restrict__ n0p = (const float4*)(nf + (size_t)b * 2 * HW);
    const float4* __restrict__ n1p = n0p + HW4;

    // Base index: all loop iterations add a whole number of rows (120),
    // so column (and x) are loop-invariant per lane.
    const int i0 = blockIdx.x * TPB + tid;
    const int h0 = i0 / W4;                 // compile-time-const divisor
    const int w0 = (i0 - h0 * W4) * 4;

    // Per-lane loop invariants
    float xv[4], xx1[4], AV0v[4];
    #pragma unroll
    for (int j = 0; j < 4; j++) {
        float x  = (float)(w0 + j);
        xv[j]    = x;
        xx1[j]   = fmaf(x, x, 1.0f);        // x^2 + 1
        AV0v[j]  = fmaf(x, V2, -V0);        // -V0 + x*V2
    }

    float acc = 0.0f;

    #pragma unroll
    for (int k = 0; k < ITERS; k++) {
        const int i = i0 + k * STRIDE4;
        float4 g0 = g0p[i];
        float4 g1 = g1p[i];
        float4 n0 = n0p[i];
        float4 n1 = n1p[i];

        const float y     = (float)(h0 + k * ROWS_PER_ITER);
        const float AV1   = fmaf(y, V2, -V1);          // -V1 + y*V2
        const float yO2   = y * O2;
        const float y2p1O0 = fmaf(y, y, 1.0f) * O0;    // (y^2+1)*O0

        const float* ga = &g0.x;
        const float* gb = &g1.x;
        const float* na = &n0.x;
        const float* nb = &n1.x;

        #pragma unroll
        for (int j = 0; j < 4; j++) {
            float x  = xv[j];
            float xy = x * y;

            // BW0 = xy*O0 - (x^2+1)*O1 + y*O2
            float BW0 = fmaf(xy, O0, fmaf(-xx1[j], O1, yO2));
            // BW1 = (y^2+1)*O0 - xy*O1 - x*O2
            float BW1 = fmaf(-xy, O1, fmaf(-x, O2, y2p1O0));

            float gg0 = ga[j], gg1 = gb[j];
            float s = fmaf(gg0, AV0v[j], gg1 * AV1);
            float t = (na[j] + nb[j]) - fmaf(gg0, BW0, gg1 * BW1);
            float z = -(s * t);

            // exact GELU: z * Phi(z)
            acc += z * normcdff(z);
        }
    }

    // ---- block reduction (float, tree) ----
    __shared__ float warp_sums[TPB / 32];
    __shared__ bool  is_last;
    const unsigned mask = 0xFFFFFFFFu;
    #pragma unroll
    for (int off = 16; off > 0; off >>= 1)
        acc += __shfl_down_sync(mask, acc, off);

    const int lane = tid & 31;
    const int wid  = tid >> 5;
    if (lane == 0) warp_sums[wid] = acc;
    __syncthreads();

    if (tid == 0) {
        float bsum = 0.0f;
        #pragma unroll
        for (int w = 0; w < TPB / 32; w++) bsum += warp_sums[w];
        const int bid = blockIdx.y * GX + blockIdx.x;
        g_partials[bid] = bsum;
        __threadfence();
        unsigned int old = atomicAdd(&g_count, 1u);
        is_last = (old == (unsigned)(NBLK - 1));
    }
    __syncthreads();

    // ---- last block finishes: sum 1200 partials in double, write out ----
    if (is_last) {
        double v = 0.0;
        for (int i = tid; i < NBLK; i += TPB)
            v += (double)g_partials[i];

        __shared__ double dsums[TPB / 32];
        #pragma unroll
        for (int off = 16; off > 0; off >>= 1)
            v += __shfl_down_sync(mask, v, off);
        if (lane == 0) dsums[wid] = v;
        __syncthreads();

        if (tid == 0) {
            double total = 0.0;
            #pragma unroll
            for (int w = 0; w < TPB / 32; w++) total += dsums[w];
            out[0] = (float)(total / (double)((long long)BN * HW));
            g_count = 0;   // reset for next graph replay (deterministic)
        }
    }
}

extern "C" void kernel_launch(void* const* d_in, const int* in_sizes, int n_in,
                              void* d_out, int out_size) {
    const float* pose = (const float*)d_in[0];
    const float* grad = (const float*)d_in[1];
    const float* nf   = (const float*)d_in[2];
    float* out = (float*)d_out;

    dim3 grid(GX, BN);
    cheirality_fused<<<grid, TPB>>>(pose, grad, nf, out);
}

// round 3
// speedup vs baseline: 2.2034x; 1.4068x over previous
#include <cuda_runtime.h>
#include <math.h>

#define BN 16
#define HH 480
#define WW 640
#define HW (HH * WW)
#define HW4 (HW / 4)            // 76800 float4 per plane
#define GX 50
#define TPB 256
#define NBLK (GX * BN)          // 800 blocks
#define STRIDE4 (GX * TPB)      // 12800 float4 stride
#define ITERS (HW4 / STRIDE4)   // exactly 6
#define W4 (WW / 4)             // 160 float4 per row
#define ROWS_PER_ITER (STRIDE4 / W4) // 80

// Allocation-free scratch.
__device__ float g_partials[NBLK];
__device__ unsigned int g_count = 0;

__global__ __launch_bounds__(TPB, 6) void cheirality_fused(
    const float* __restrict__ pose,
    const float* __restrict__ grad,
    const float* __restrict__ nf,
    float* __restrict__ out)
{
    const int b   = blockIdx.y;
    const int tid = threadIdx.x;

    const float V0 = __ldg(pose + b * 6 + 0);
    const float V1 = __ldg(pose + b * 6 + 1);
    const float V2 = __ldg(pose + b * 6 + 2);
    const float O0 = __ldg(pose + b * 6 + 3);
    const float O1 = __ldg(pose + b * 6 + 4);
    const float O2 = __ldg(pose + b * 6 + 5);

    const float4* __restrict__ g0p = (const float4*)(grad + (size_t)b * 2 * HW);
    const float4* __restrict__ g1p = g0p + HW4;
    const float4* __restrict__ n0p = (const float4*)(nf + (size_t)b * 2 * HW);
    const float4* __restrict__ n1p = n0p + HW4;

    // Stride is a whole number of rows (80), so the column is loop-invariant.
    const int i0 = blockIdx.x * TPB + tid;
    const int h0 = i0 / W4;                    // const divisor -> mul/shift
    const float x0 = (float)((i0 - h0 * W4) * 4);

    float acc = 0.0f;

    #pragma unroll
    for (int k = 0; k < ITERS; k++) {
        const int i = i0 + k * STRIDE4;
        float4 g0 = g0p[i];
        float4 g1 = g1p[i];
        float4 n0 = n0p[i];
        float4 n1 = n1p[i];

        const float y      = (float)(h0 + k * ROWS_PER_ITER);
        const float AV1    = fmaf(y, V2, -V1);          // -V1 + y*V2
        const float yO2    = y * O2;
        const float y2p1O0 = fmaf(y, y, 1.0f) * O0;     // (y^2+1)*O0
        const float yO0    = y * O0;                    // for xy*O0 = x*(y*O0)
        const float yO1    = y * O1;

        const float* ga = &g0.x;
        const float* gb = &g1.x;
        const float* na = &n0.x;
        const float* nb = &n1.x;

        #pragma unroll
        for (int j = 0; j < 4; j++) {
            const float x = x0 + (float)j;

            const float AV0 = fmaf(x, V2, -V0);                       // -V0 + x*V2
            // BW0 = x*(y*O0) - (x^2+1)*O1 + y*O2
            const float BW0 = fmaf(x, yO0, fmaf(-fmaf(x, x, 1.0f), O1, yO2));
            // BW1 = (y^2+1)*O0 - x*(y*O1) - x*O2
            const float BW1 = fmaf(-x, yO1, fmaf(-x, O2, y2p1O0));

            const float gg0 = ga[j], gg1 = gb[j];
            const float s = fmaf(gg0, AV0, gg1 * AV1);
            const float t = (na[j] + nb[j]) - fmaf(gg0, BW0, gg1 * BW1);
            const float z = -(s * t);

            // Exact GELU. For |z| >= 16, z*Phi(z) == max(z,0) to < 1e-50 abs,
            // so the expensive erfc path runs only on the (measure-zero) strip.
            float val = fmaxf(z, 0.0f);
            if (fabsf(z) < 16.0f) val = z * normcdff(z);
            acc += val;
        }
    }

    // ---- block reduction (float tree) ----
    __shared__ float warp_sums[TPB / 32];
    __shared__ bool  is_last;
    const unsigned mask = 0xFFFFFFFFu;
    #pragma unroll
    for (int off = 16; off > 0; off >>= 1)
        acc += __shfl_down_sync(mask, acc, off);

    const int lane = tid & 31;
    const int wid  = tid >> 5;
    if (lane == 0) warp_sums[wid] = acc;
    __syncthreads();

    if (tid == 0) {
        float bsum = 0.0f;
        #pragma unroll
        for (int w = 0; w < TPB / 32; w++) bsum += warp_sums[w];
        g_partials[blockIdx.y * GX + blockIdx.x] = bsum;
        __threadfence();
        unsigned int old = atomicAdd(&g_count, 1u);
        is_last = (old == (unsigned)(NBLK - 1));
    }
    __syncthreads();

    // ---- last block: sum partials in double, write scalar ----
    if (is_last) {
        double v = 0.0;
        for (int i = tid; i < NBLK; i += TPB)
            v += (double)g_partials[i];

        __shared__ double dsums[TPB / 32];
        #pragma unroll
        for (int off = 16; off > 0; off >>= 1)
            v += __shfl_down_sync(mask, v, off);
        if (lane == 0) dsums[wid] = v;
        __syncthreads();

        if (tid == 0) {
            double total = 0.0;
            #pragma unroll
            for (int w = 0; w < TPB / 32; w++) total += dsums[w];
            out[0] = (float)(total / (double)((long long)BN * HW));
            g_count = 0;   // reset for next graph replay
        }
    }
}

extern "C" void kernel_launch(void* const* d_in, const int* in_sizes, int n_in,
                              void* d_out, int out_size) {
    const float* pose = (const float*)d_in[0];
    const float* grad = (const float*)d_in[1];
    const float* nf   = (const float*)d_in[2];
    float* out = (float*)d_out;

    dim3 grid(GX, BN);
    cheirality_fused<<<grid, TPB>>>(pose, grad, nf, out);
}